// round 14
// baseline (speedup 1.0000x reference)
#include <cuda_runtime.h>
#include <cuda_fp16.h>
#include <math.h>
#include <stdint.h>

#define NN 100000
#define NE 1600000
#define F  128
#define SCAN_B 512
#define NBLK ((NN + SCAN_B - 1) / SCAN_B)   // 196

// Scratch (allocation-free rule: __device__ globals)
__device__ __half g_h[(size_t)NN * F];     // GEMM1 out (fp16)
__device__ __half g_h2[(size_t)NN * F];    // fused out (fp16)
__device__ __half g_w2h[F * F];            // fp16 copy of W2
__device__ int    g_cnt[NN];               // zero at sequence start & end
__device__ int    g_rptr[NN + 1];
__device__ int    g_end[NN];               // inclusive ends; consumed by place
__device__ int    g_scol[NE];
__device__ int    g_part[SCAN_B];

// Host-side fork resources (created once at load; host objects only)
static cudaStream_t g_side;
static cudaEvent_t g_ev_fork, g_ev_csr;
namespace {
struct HostInit {
  HostInit() {
    cudaStreamCreateWithFlags(&g_side, cudaStreamNonBlocking);
    cudaEventCreateWithFlags(&g_ev_fork, cudaEventDisableTiming);
    cudaEventCreateWithFlags(&g_ev_csr, cudaEventDisableTiming);
  }
};
HostInit host_init_;
}

// ================= CSR build =================
__global__ void k_hist(const int* __restrict__ row) {
  int e = (blockIdx.x * blockDim.x + threadIdx.x) * 4;
  if (e + 3 < NE) {
    int4 r = *(const int4*)(row + e);
    atomicAdd(&g_cnt[r.x], 1);
    atomicAdd(&g_cnt[r.y], 1);
    atomicAdd(&g_cnt[r.z], 1);
    atomicAdd(&g_cnt[r.w], 1);
  } else {
    for (; e < NE; e++) atomicAdd(&g_cnt[row[e]], 1);
  }
}

__global__ __launch_bounds__(SCAN_B) void k_scanA() {
  __shared__ int sh[SCAN_B];
  int g = blockIdx.x * SCAN_B + threadIdx.x;
  int v = 0;
  if (g < NN) {
    v = g_cnt[g];
    g_cnt[g] = 0;                         // restore invariant for next call
  }
  sh[threadIdx.x] = v;
  __syncthreads();
#pragma unroll
  for (int off = 1; off < SCAN_B; off <<= 1) {
    int t = (threadIdx.x >= off) ? sh[threadIdx.x - off] : 0;
    __syncthreads();
    sh[threadIdx.x] += t;
    __syncthreads();
  }
  if (g < NN) {
    g_rptr[g] = sh[threadIdx.x] - v;
    g_end[g]  = sh[threadIdx.x];
  }
  if (threadIdx.x == SCAN_B - 1) g_part[blockIdx.x] = sh[SCAN_B - 1];
}

__global__ __launch_bounds__(SCAN_B) void k_scanBC() {
  __shared__ int red[SCAN_B];
  int b = blockIdx.x;
  red[threadIdx.x] = (threadIdx.x < b && threadIdx.x < NBLK) ? g_part[threadIdx.x] : 0;
  __syncthreads();
#pragma unroll
  for (int off = SCAN_B / 2; off > 0; off >>= 1) {
    if (threadIdx.x < off) red[threadIdx.x] += red[threadIdx.x + off];
    __syncthreads();
  }
  int offset = red[0];
  int g = b * SCAN_B + threadIdx.x;
  if (g < NN) {
    g_rptr[g] += offset;
    g_end[g]  += offset;
  }
  if (g == 0) g_rptr[NN] = NE;
}

__global__ void k_place(const int* __restrict__ row, const int* __restrict__ col) {
  int e = blockIdx.x * blockDim.x + threadIdx.x;
  if (e >= NE) return;
  int pos = atomicSub(&g_end[row[e]], 1) - 1;
  g_scol[pos] = col[e];
}

// ================= W2 -> fp16 pre-convert (off critical path) =================
__global__ void k_cvt_w(const float* __restrict__ W, __half* __restrict__ Wh) {
  int i = (blockIdx.x * blockDim.x + threadIdx.x) * 4;
  if (i < F * F) {
    float4 v = *(const float4*)(W + i);
    *(__half2*)(Wh + i)     = __floats2half2_rn(v.x, v.y);
    *(__half2*)(Wh + i + 2) = __floats2half2_rn(v.z, v.w);
  }
}

// ================= fp16 mma.sync GEMM core =================
#define H_STRIDE 136                        // halves per row (128 + 8 pad)
#define TILE_HALVES (128 * H_STRIDE)        // 17408
#define GEMM_SMEM (2 * TILE_HALVES * 2)     // 69632 B

__device__ __forceinline__ void mma_f16(float* c, const uint32_t* a, const uint32_t* b) {
  asm volatile(
      "mma.sync.aligned.m16n8k16.row.col.f32.f16.f16.f32 "
      "{%0,%1,%2,%3}, {%4,%5,%6,%7}, {%8,%9}, {%0,%1,%2,%3};"
      : "+f"(c[0]), "+f"(c[1]), "+f"(c[2]), "+f"(c[3])
      : "r"(a[0]), "r"(a[1]), "r"(a[2]), "r"(a[3]), "r"(b[0]), "r"(b[1]));
}

__device__ __forceinline__ void gemm_compute(
    const __half* sA, const __half* sW, float acc[2][8][4],
    int wm, int wn, int g, int t) {
#pragma unroll
  for (int k16 = 0; k16 < 8; k16++) {
    const int kc = k16 * 16;
    uint32_t af[2][4];
#pragma unroll
    for (int mt = 0; mt < 2; mt++) {
      const __half* base = sA + (size_t)(wm * 32 + mt * 16 + g) * H_STRIDE + kc;
      af[mt][0] = *(const uint32_t*)(base + 2 * t);
      af[mt][1] = *(const uint32_t*)(base + 8 * H_STRIDE + 2 * t);
      af[mt][2] = *(const uint32_t*)(base + 2 * t + 8);
      af[mt][3] = *(const uint32_t*)(base + 8 * H_STRIDE + 2 * t + 8);
    }
#pragma unroll
    for (int nt = 0; nt < 8; nt++) {
      const __half* wbase = sW + (size_t)(wn * 64 + nt * 8 + g) * H_STRIDE + kc;
      uint32_t bf[2];
      bf[0] = *(const uint32_t*)(wbase + 2 * t);
      bf[1] = *(const uint32_t*)(wbase + 2 * t + 8);
#pragma unroll
      for (int mt = 0; mt < 2; mt++) mma_f16(acc[mt][nt], af[mt], bf);
    }
  }
}

__device__ __forceinline__ void gemm_epilogue(
    float acc[2][8][4], const float* __restrict__ bias,
    __half* __restrict__ C, int M, int m0, int wm, int wn, int g, int t) {
#pragma unroll
  for (int mt = 0; mt < 2; mt++) {
    int row0 = m0 + wm * 32 + mt * 16 + g;
#pragma unroll
    for (int nt = 0; nt < 8; nt++) {
      int col = wn * 64 + nt * 8 + t * 2;
      float bx = __ldg(bias + col);
      float by = __ldg(bias + col + 1);
      if (row0 < M) {
        __half2 o = __floats2half2_rn(acc[mt][nt][0] + bx, acc[mt][nt][1] + by);
        *(__half2*)(C + (size_t)row0 * F + col) = o;
      }
      if (row0 + 8 < M) {
        __half2 o = __floats2half2_rn(acc[mt][nt][2] + bx, acc[mt][nt][3] + by);
        *(__half2*)(C + (size_t)(row0 + 8) * F + col) = o;
      }
    }
  }
}

// Layer 1 GEMM: A fp32 convert-on-load (hidden behind CSR build)
__global__ __launch_bounds__(256, 2) void k_gemm_tc(
    const float* __restrict__ A, const float* __restrict__ W,
    const float* __restrict__ bias, __half* __restrict__ C, int M) {
  extern __shared__ __half sh[];
  __half* sA = sh;
  __half* sW = sh + TILE_HALVES;
  const int tid = threadIdx.x;
  const int wid = tid >> 5;
  const int lane = tid & 31;
  const int m0 = blockIdx.x * 128;

#pragma unroll
  for (int it = 0; it < 16; it++) {
    int idx = it * 256 + tid;
    int row = idx >> 5;
    int cq = idx & 31;

    float4 va = make_float4(0.f, 0.f, 0.f, 0.f);
    if (m0 + row < M)
      va = *(const float4*)(A + (size_t)(m0 + row) * F + cq * 4);
    *(__half2*)&sA[row * H_STRIDE + cq * 4]     = __floats2half2_rn(va.x, va.y);
    *(__half2*)&sA[row * H_STRIDE + cq * 4 + 2] = __floats2half2_rn(va.z, va.w);

    float4 vw = *(const float4*)(W + (size_t)row * F + cq * 4);
    *(__half2*)&sW[row * H_STRIDE + cq * 4]     = __floats2half2_rn(vw.x, vw.y);
    *(__half2*)&sW[row * H_STRIDE + cq * 4 + 2] = __floats2half2_rn(vw.z, vw.w);
  }
  __syncthreads();

  float acc[2][8][4];
#pragma unroll
  for (int i = 0; i < 2; i++)
#pragma unroll
    for (int j = 0; j < 8; j++)
#pragma unroll
      for (int l = 0; l < 4; l++) acc[i][j][l] = 0.0f;
  gemm_compute(sA, sW, acc, wid & 3, wid >> 2, lane >> 2, lane & 3);
  gemm_epilogue(acc, bias, C, M, m0, wid & 3, wid >> 2, lane >> 2, lane & 3);
}

// ================= gather helper =================
__device__ __forceinline__ void acc_edge(float4& acc, const __half* src, int c, int lane) {
  uint2 v = ((const uint2*)(src + (size_t)c * F))[lane];
  float2 f0 = __half22float2(*(__half2*)&v.x);
  float2 f1 = __half22float2(*(__half2*)&v.y);
  acc.x += f0.x; acc.y += f0.y; acc.z += f1.x; acc.w += f1.y;
}

__device__ __forceinline__ float4 gather_node(const __half* __restrict__ src,
                                              int node, int lane) {
  int s = g_rptr[node];
  int e = g_rptr[node + 1];
  float4 acc = make_float4(0.f, 0.f, 0.f, 0.f);
  int j = s;
  for (; j + 4 <= e; j += 4) {
    int c0 = __ldg(&g_scol[j + 0]);
    int c1 = __ldg(&g_scol[j + 1]);
    int c2 = __ldg(&g_scol[j + 2]);
    int c3 = __ldg(&g_scol[j + 3]);
    acc_edge(acc, src, c0, lane);
    acc_edge(acc, src, c1, lane);
    acc_edge(acc, src, c2, lane);
    acc_edge(acc, src, c3, lane);
  }
  for (; j < e; j++) acc_edge(acc, src, __ldg(&g_scol[j]), lane);
  float inv = (e > s) ? 1.0f / (float)(e - s) : 0.0f;
  acc.x *= inv; acc.y *= inv; acc.z *= inv; acc.w *= inv;
  return acc;
}

// ================= FUSED: gather1(+ELU) -> smem A-tile -> GEMM2 =================
// One block = one 128-row GEMM tile. Phase 1: 8 warps gather 16 nodes each
// (mean + ELU, fp16) straight into sA. W2 tile streams via cp.async meanwhile.
__global__ __launch_bounds__(256, 2) void k_fused_g1_gemm2(
    const __half* __restrict__ h, const __half* __restrict__ Wh,
    const float* __restrict__ bias, __half* __restrict__ C, int M) {
  extern __shared__ __half sh[];
  __half* sA = sh;
  __half* sW = sh + TILE_HALVES;
  const int tid = threadIdx.x;
  const int wid = tid >> 5;
  const int lane = tid & 31;
  const int m0 = blockIdx.x * 128;

  // Kick off W tile load (128 rows x 16 chunks of 16B = 2048; 8/thread)
#pragma unroll
  for (int it = 0; it < 8; it++) {
    int idx = it * 256 + tid;
    int row = idx >> 4;
    int c8 = idx & 15;
    uint32_t dst = (uint32_t)__cvta_generic_to_shared(
        sW + (size_t)row * H_STRIDE + c8 * 8);
    asm volatile("cp.async.ca.shared.global [%0], [%1], 16;"
                 :: "r"(dst), "l"(Wh + (size_t)row * F + c8 * 8));
  }
  asm volatile("cp.async.commit_group;");

  // Phase 1: gather + ELU into sA (lane owns halves [lane*4, lane*4+4))
#pragma unroll 1
  for (int i = 0; i < 16; i++) {
    int r = wid * 16 + i;
    int node = m0 + r;
    float4 acc = make_float4(0.f, 0.f, 0.f, 0.f);
    if (node < M) acc = gather_node(h, node, lane);
    acc.x = acc.x > 0.f ? acc.x : expm1f(acc.x);
    acc.y = acc.y > 0.f ? acc.y : expm1f(acc.y);
    acc.z = acc.z > 0.f ? acc.z : expm1f(acc.z);
    acc.w = acc.w > 0.f ? acc.w : expm1f(acc.w);
    uint2 o;
    *(__half2*)&o.x = __floats2half2_rn(acc.x, acc.y);
    *(__half2*)&o.y = __floats2half2_rn(acc.z, acc.w);
    *(uint2*)&sA[(size_t)r * H_STRIDE + lane * 4] = o;
  }
  asm volatile("cp.async.wait_group 0;");
  __syncthreads();

  // Phase 2: GEMM tile
  float acc[2][8][4];
#pragma unroll
  for (int i = 0; i < 2; i++)
#pragma unroll
    for (int j = 0; j < 8; j++)
#pragma unroll
      for (int l = 0; l < 4; l++) acc[i][j][l] = 0.0f;
  gemm_compute(sA, sW, acc, wid & 3, wid >> 2, lane >> 2, lane & 3);
  gemm_epilogue(acc, bias, C, M, m0, wid & 3, wid >> 2, lane >> 2, lane & 3);
}

// ================= final gather: mean only, fp32 out =================
__global__ __launch_bounds__(256) void k_gather_out(
    const __half* __restrict__ src, float* __restrict__ dst) {
  int node = blockIdx.x * 8 + (threadIdx.x >> 5);
  if (node >= NN) return;
  int lane = threadIdx.x & 31;
  float4 acc = gather_node(src, node, lane);
  ((float4*)(dst + (size_t)node * F))[lane] = acc;
}

extern "C" void kernel_launch(void* const* d_in, const int* in_sizes, int n_in,
                              void* d_out, int out_size) {
  const float* x  = (const float*)d_in[0];
  const int*   ei = (const int*)d_in[1];
  const float* W1 = (const float*)d_in[2];
  const float* b1 = (const float*)d_in[3];
  const float* W2 = (const float*)d_in[4];
  const float* b2 = (const float*)d_in[5];
  const int* row = ei;
  const int* col = ei + NE;
  float* out = (float*)d_out;

  void* p_h = nullptr;
  void* p_h2 = nullptr;
  void* p_w2h = nullptr;
  cudaGetSymbolAddress(&p_h, g_h);
  cudaGetSymbolAddress(&p_h2, g_h2);
  cudaGetSymbolAddress(&p_w2h, g_w2h);
  __half* h   = (__half*)p_h;
  __half* h2  = (__half*)p_h2;
  __half* w2h = (__half*)p_w2h;

  cudaFuncSetAttribute(k_gemm_tc, cudaFuncAttributeMaxDynamicSharedMemorySize, GEMM_SMEM);
  cudaFuncSetAttribute(k_fused_g1_gemm2, cudaFuncAttributeMaxDynamicSharedMemorySize, GEMM_SMEM);

  const int gblocks = (NN + 127) / 128;       // 782
  const int eblocks1 = (NE + 511) / 512;      // 3125
  const int eblocks4 = (NE / 4 + 511) / 512;  // 782

  // ---- fork: CSR build on side stream, W2-convert + GEMM1 on main ----
  cudaEventRecord(g_ev_fork, 0);
  cudaStreamWaitEvent(g_side, g_ev_fork, 0);

  k_hist<<<eblocks4, 512, 0, g_side>>>(row);
  k_scanA<<<NBLK, SCAN_B, 0, g_side>>>();
  k_scanBC<<<NBLK, SCAN_B, 0, g_side>>>();
  k_place<<<eblocks1, 512, 0, g_side>>>(row, col);
  cudaEventRecord(g_ev_csr, g_side);

  k_cvt_w<<<(F * F / 4 + 255) / 256, 256>>>(W2, w2h);              // W2 -> fp16
  k_gemm_tc<<<gblocks, 256, GEMM_SMEM>>>(x, W1, b1, h, NN);        // h = x W1^T + b1

  // ---- join, then fused gather1+GEMM2, then final gather ----
  cudaStreamWaitEvent(0, g_ev_csr, 0);
  k_fused_g1_gemm2<<<gblocks, 256, GEMM_SMEM>>>(h, w2h, b2, h2, NN);
  k_gather_out<<<(NN + 7) / 8, 256>>>(h2, out);                    // out = mean(h2)
}

// round 15
// speedup vs baseline: 1.3745x; 1.3745x over previous
#include <cuda_runtime.h>
#include <cuda_fp16.h>
#include <math.h>
#include <stdint.h>

#define NN 100000
#define NE 1600000
#define NE_HALF (NE / 2)
#define F  128
#define SCAN_B 512
#define NBLK ((NN + SCAN_B - 1) / SCAN_B)   // 196

// Scratch (allocation-free rule: __device__ globals)
__device__ __half g_h[(size_t)NN * F];     // fp16 intermediate (reused by both layers)
__device__ __half g_agg[(size_t)NN * F];   // fp16 intermediate
__device__ __half g_w2h[F * F];            // fp16 copy of W2
__device__ int    g_cnt0[NN];              // per-half histograms; zero at start & end
__device__ int    g_cnt1[NN];
__device__ int    g_rptr[NN + 1];
__device__ int    g_end0[NN];              // placement cursors (consumed by place)
__device__ int    g_end1[NN];
__device__ int    g_scol[NE];
__device__ int    g_part[SCAN_B];

// Host-side fork resources (created once at load; host objects only)
static cudaStream_t g_side;
static cudaEvent_t g_ev_fork, g_ev_csr;
namespace {
struct HostInit {
  HostInit() {
    cudaStreamCreateWithFlags(&g_side, cudaStreamNonBlocking);
    cudaEventCreateWithFlags(&g_ev_fork, cudaEventDisableTiming);
    cudaEventCreateWithFlags(&g_ev_csr, cudaEventDisableTiming);
  }
};
HostInit host_init_;
}

// ================= CSR build (split-bucket: halved atomic contention) =================
// hist: 4 edges/thread; first-half edges count in cnt0, second-half in cnt1.
// Spare capacity converts W2 -> fp16 (removes a main-stream kernel).
__global__ void k_hist(const int* __restrict__ row,
                       const float* __restrict__ W2, __half* __restrict__ Wh) {
  int t = blockIdx.x * blockDim.x + threadIdx.x;
  if (t < F * F / 4) {
    float4 v = *(const float4*)(W2 + t * 4);
    *(__half2*)(Wh + t * 4)     = __floats2half2_rn(v.x, v.y);
    *(__half2*)(Wh + t * 4 + 2) = __floats2half2_rn(v.z, v.w);
  }
  int e = t * 4;
  if (e + 3 < NE) {
    int4 r = *(const int4*)(row + e);
    int* cnt = (e < NE_HALF) ? g_cnt0 : g_cnt1;   // 4-packs never straddle halves
    atomicAdd(&cnt[r.x], 1);
    atomicAdd(&cnt[r.y], 1);
    atomicAdd(&cnt[r.z], 1);
    atomicAdd(&cnt[r.w], 1);
  } else {
    for (; e < NE; e++)
      atomicAdd(&((e < NE_HALF) ? g_cnt0 : g_cnt1)[row[e]], 1);
  }
}

// Block-local exclusive scan over (cnt0+cnt1); zeroes both; writes rptr + cursors.
__global__ __launch_bounds__(SCAN_B) void k_scanA() {
  __shared__ int sh[SCAN_B];
  int g = blockIdx.x * SCAN_B + threadIdx.x;
  int v0 = 0, v1 = 0;
  if (g < NN) {
    v0 = g_cnt0[g]; g_cnt0[g] = 0;        // restore invariant for next call
    v1 = g_cnt1[g]; g_cnt1[g] = 0;
  }
  int v = v0 + v1;
  sh[threadIdx.x] = v;
  __syncthreads();
#pragma unroll
  for (int off = 1; off < SCAN_B; off <<= 1) {
    int t = (threadIdx.x >= off) ? sh[threadIdx.x - off] : 0;
    __syncthreads();
    sh[threadIdx.x] += t;
    __syncthreads();
  }
  if (g < NN) {
    int incl = sh[threadIdx.x];
    g_rptr[g] = incl - v;                 // exclusive (pre-offset)
    g_end0[g] = incl - v1;                // end of bucket0 = rptr + cnt0
    g_end1[g] = incl;                     // end of bucket1 = rptr[i+1]
  }
  if (threadIdx.x == SCAN_B - 1) g_part[blockIdx.x] = sh[SCAN_B - 1];
}

// Each block reduces partials below it, adds offset to rptr and both cursors.
__global__ __launch_bounds__(SCAN_B) void k_scanBC() {
  __shared__ int red[SCAN_B];
  int b = blockIdx.x;
  red[threadIdx.x] = (threadIdx.x < b && threadIdx.x < NBLK) ? g_part[threadIdx.x] : 0;
  __syncthreads();
#pragma unroll
  for (int off = SCAN_B / 2; off > 0; off >>= 1) {
    if (threadIdx.x < off) red[threadIdx.x] += red[threadIdx.x + off];
    __syncthreads();
  }
  int offset = red[0];
  int g = b * SCAN_B + threadIdx.x;
  if (g < NN) {
    g_rptr[g] += offset;
    g_end0[g] += offset;
    g_end1[g] += offset;
  }
  if (g == 0) g_rptr[NN] = NE;
}

// Placement: 1 edge/thread; each half decrements its own cursor array
// (2x address space -> half the same-address atomic collisions).
__global__ void k_place(const int* __restrict__ row, const int* __restrict__ col) {
  int e = blockIdx.x * blockDim.x + threadIdx.x;
  if (e >= NE) return;
  int r = row[e];
  int pos = (e < NE_HALF) ? (atomicSub(&g_end0[r], 1) - 1)
                          : (atomicSub(&g_end1[r], 1) - 1);
  g_scol[pos] = col[e];
}

// ================= fp16 mma.sync GEMM core =================
#define H_STRIDE 136                        // halves per row (128 + 8 pad)
#define TILE_HALVES (128 * H_STRIDE)        // 17408
#define GEMM_SMEM (2 * TILE_HALVES * 2)     // 69632 B

__device__ __forceinline__ void mma_f16(float* c, const uint32_t* a, const uint32_t* b) {
  asm volatile(
      "mma.sync.aligned.m16n8k16.row.col.f32.f16.f16.f32 "
      "{%0,%1,%2,%3}, {%4,%5,%6,%7}, {%8,%9}, {%0,%1,%2,%3};"
      : "+f"(c[0]), "+f"(c[1]), "+f"(c[2]), "+f"(c[3])
      : "r"(a[0]), "r"(a[1]), "r"(a[2]), "r"(a[3]), "r"(b[0]), "r"(b[1]));
}

// Compute k16 range [k0,k1) accumulating into acc.
__device__ __forceinline__ void gemm_compute(
    const __half* sA, const __half* sW, float acc[2][8][4],
    int k0, int k1, int wm, int wn, int g, int t) {
#pragma unroll
  for (int k16 = 0; k16 < 8; k16++) {
    if (k16 < k0 || k16 >= k1) continue;
    const int kc = k16 * 16;
    uint32_t af[2][4];
#pragma unroll
    for (int mt = 0; mt < 2; mt++) {
      const __half* base = sA + (size_t)(wm * 32 + mt * 16 + g) * H_STRIDE + kc;
      af[mt][0] = *(const uint32_t*)(base + 2 * t);
      af[mt][1] = *(const uint32_t*)(base + 8 * H_STRIDE + 2 * t);
      af[mt][2] = *(const uint32_t*)(base + 2 * t + 8);
      af[mt][3] = *(const uint32_t*)(base + 8 * H_STRIDE + 2 * t + 8);
    }
#pragma unroll
    for (int nt = 0; nt < 8; nt++) {
      const __half* wbase = sW + (size_t)(wn * 64 + nt * 8 + g) * H_STRIDE + kc;
      uint32_t bf[2];
      bf[0] = *(const uint32_t*)(wbase + 2 * t);
      bf[1] = *(const uint32_t*)(wbase + 2 * t + 8);
#pragma unroll
      for (int mt = 0; mt < 2; mt++) mma_f16(acc[mt][nt], af[mt], bf);
    }
  }
}

__device__ __forceinline__ void gemm_epilogue(
    float acc[2][8][4], const float* __restrict__ bias,
    __half* __restrict__ C, int M, int m0, int wm, int wn, int g, int t) {
#pragma unroll
  for (int mt = 0; mt < 2; mt++) {
    int row0 = m0 + wm * 32 + mt * 16 + g;
#pragma unroll
    for (int nt = 0; nt < 8; nt++) {
      int col = wn * 64 + nt * 8 + t * 2;
      float bx = __ldg(bias + col);
      float by = __ldg(bias + col + 1);
      if (row0 < M) {
        __half2 o = __floats2half2_rn(acc[mt][nt][0] + bx, acc[mt][nt][1] + by);
        *(__half2*)(C + (size_t)row0 * F + col) = o;
      }
      if (row0 + 8 < M) {
        __half2 o = __floats2half2_rn(acc[mt][nt][2] + bx, acc[mt][nt][3] + by);
        *(__half2*)(C + (size_t)(row0 + 8) * F + col) = o;
      }
    }
  }
}

// Layer 1 GEMM: A fp32 convert-on-load (hidden behind CSR build)
__global__ __launch_bounds__(256, 2) void k_gemm_tc(
    const float* __restrict__ A, const float* __restrict__ W,
    const float* __restrict__ bias, __half* __restrict__ C, int M) {
  extern __shared__ __half sh[];
  __half* sA = sh;
  __half* sW = sh + TILE_HALVES;
  const int tid = threadIdx.x;
  const int wid = tid >> 5;
  const int lane = tid & 31;
  const int m0 = blockIdx.x * 128;

#pragma unroll
  for (int it = 0; it < 16; it++) {
    int idx = it * 256 + tid;
    int row = idx >> 5;
    int cq = idx & 31;

    float4 va = make_float4(0.f, 0.f, 0.f, 0.f);
    if (m0 + row < M)
      va = *(const float4*)(A + (size_t)(m0 + row) * F + cq * 4);
    *(__half2*)&sA[row * H_STRIDE + cq * 4]     = __floats2half2_rn(va.x, va.y);
    *(__half2*)&sA[row * H_STRIDE + cq * 4 + 2] = __floats2half2_rn(va.z, va.w);

    float4 vw = *(const float4*)(W + (size_t)row * F + cq * 4);
    *(__half2*)&sW[row * H_STRIDE + cq * 4]     = __floats2half2_rn(vw.x, vw.y);
    *(__half2*)&sW[row * H_STRIDE + cq * 4 + 2] = __floats2half2_rn(vw.z, vw.w);
  }
  __syncthreads();

  float acc[2][8][4];
#pragma unroll
  for (int i = 0; i < 2; i++)
#pragma unroll
    for (int j = 0; j < 8; j++)
#pragma unroll
      for (int l = 0; l < 4; l++) acc[i][j][l] = 0.0f;
  gemm_compute(sA, sW, acc, 0, 8, wid & 3, wid >> 2, lane >> 2, lane & 3);
  gemm_epilogue(acc, bias, C, M, m0, wid & 3, wid >> 2, lane >> 2, lane & 3);
}

// Layer 2 GEMM: A and W both fp16; cp.async 2-stage K-pipeline
__global__ __launch_bounds__(256, 2) void k_gemm_tc_h(
    const __half* __restrict__ A, const __half* __restrict__ Wh,
    const float* __restrict__ bias, __half* __restrict__ C, int M) {
  extern __shared__ __half sh[];
  __half* sA = sh;
  __half* sW = sh + TILE_HALVES;
  const int tid = threadIdx.x;
  const int wid = tid >> 5;
  const int lane = tid & 31;
  const int m0 = blockIdx.x * 128;

#pragma unroll
  for (int half = 0; half < 2; half++) {
    const int hofs = half * 64;
#pragma unroll
    for (int it = 0; it < 4; it++) {
      int idx = it * 256 + tid;
      int row = idx >> 3;
      int c8 = idx & 7;
      {
        uint32_t dst = (uint32_t)__cvta_generic_to_shared(
            sA + (size_t)row * H_STRIDE + hofs + c8 * 8);
        const __half* src = A + (size_t)(m0 + row) * F + hofs + c8 * 8;
        int sz = (m0 + row < M) ? 16 : 0;
        asm volatile("cp.async.ca.shared.global [%0], [%1], 16, %2;"
                     :: "r"(dst), "l"(src), "r"(sz));
      }
      {
        uint32_t dst = (uint32_t)__cvta_generic_to_shared(
            sW + (size_t)row * H_STRIDE + hofs + c8 * 8);
        const __half* src = Wh + (size_t)row * F + hofs + c8 * 8;
        asm volatile("cp.async.ca.shared.global [%0], [%1], 16;"
                     :: "r"(dst), "l"(src));
      }
    }
    asm volatile("cp.async.commit_group;");
  }

  float acc[2][8][4];
#pragma unroll
  for (int i = 0; i < 2; i++)
#pragma unroll
    for (int j = 0; j < 8; j++)
#pragma unroll
      for (int l = 0; l < 4; l++) acc[i][j][l] = 0.0f;

  const int wm = wid & 3, wn = wid >> 2, g = lane >> 2, t = lane & 3;

  asm volatile("cp.async.wait_group 1;");
  __syncthreads();
  gemm_compute(sA, sW, acc, 0, 4, wm, wn, g, t);

  asm volatile("cp.async.wait_group 0;");
  __syncthreads();
  gemm_compute(sA, sW, acc, 4, 8, wm, wn, g, t);

  gemm_epilogue(acc, bias, C, M, m0, wm, wn, g, t);
}

// ================= CSR gather SpMM (fp16 src) + mean =================
__device__ __forceinline__ void acc_edge(float4& acc, const __half* src, int c, int lane) {
  uint2 v = ((const uint2*)(src + (size_t)c * F))[lane];
  float2 f0 = __half22float2(*(__half2*)&v.x);
  float2 f1 = __half22float2(*(__half2*)&v.y);
  acc.x += f0.x; acc.y += f0.y; acc.z += f1.x; acc.w += f1.y;
}

// MODE 0: ELU + fp16 out. MODE 1: no ELU + fp32 out.
template <int MODE>
__global__ __launch_bounds__(256) void k_gather(
    const __half* __restrict__ src, void* __restrict__ dst_) {
  int node = blockIdx.x * 8 + (threadIdx.x >> 5);
  if (node >= NN) return;
  int lane = threadIdx.x & 31;

  int s = g_rptr[node];
  int e = g_rptr[node + 1];

  float4 acc = make_float4(0.f, 0.f, 0.f, 0.f);
  int j = s;
  for (; j + 4 <= e; j += 4) {
    int c0 = __ldg(&g_scol[j + 0]);
    int c1 = __ldg(&g_scol[j + 1]);
    int c2 = __ldg(&g_scol[j + 2]);
    int c3 = __ldg(&g_scol[j + 3]);
    acc_edge(acc, src, c0, lane);
    acc_edge(acc, src, c1, lane);
    acc_edge(acc, src, c2, lane);
    acc_edge(acc, src, c3, lane);
  }
  for (; j < e; j++) acc_edge(acc, src, __ldg(&g_scol[j]), lane);

  float inv = (e > s) ? 1.0f / (float)(e - s) : 0.0f;
  acc.x *= inv; acc.y *= inv; acc.z *= inv; acc.w *= inv;
  if (MODE == 0) {
    acc.x = acc.x > 0.f ? acc.x : expm1f(acc.x);
    acc.y = acc.y > 0.f ? acc.y : expm1f(acc.y);
    acc.z = acc.z > 0.f ? acc.z : expm1f(acc.z);
    acc.w = acc.w > 0.f ? acc.w : expm1f(acc.w);
    __half* dst = (__half*)dst_;
    uint2 o;
    *(__half2*)&o.x = __floats2half2_rn(acc.x, acc.y);
    *(__half2*)&o.y = __floats2half2_rn(acc.z, acc.w);
    ((uint2*)(dst + (size_t)node * F))[lane] = o;
  } else {
    float* dst = (float*)dst_;
    ((float4*)(dst + (size_t)node * F))[lane] = acc;
  }
}

extern "C" void kernel_launch(void* const* d_in, const int* in_sizes, int n_in,
                              void* d_out, int out_size) {
  const float* x  = (const float*)d_in[0];
  const int*   ei = (const int*)d_in[1];
  const float* W1 = (const float*)d_in[2];
  const float* b1 = (const float*)d_in[3];
  const float* W2 = (const float*)d_in[4];
  const float* b2 = (const float*)d_in[5];
  const int* row = ei;
  const int* col = ei + NE;
  float* out = (float*)d_out;

  void* p_h = nullptr;
  void* p_agg = nullptr;
  void* p_w2h = nullptr;
  cudaGetSymbolAddress(&p_h, g_h);
  cudaGetSymbolAddress(&p_agg, g_agg);
  cudaGetSymbolAddress(&p_w2h, g_w2h);
  __half* h   = (__half*)p_h;
  __half* agg = (__half*)p_agg;
  __half* w2h = (__half*)p_w2h;

  cudaFuncSetAttribute(k_gemm_tc, cudaFuncAttributeMaxDynamicSharedMemorySize, GEMM_SMEM);
  cudaFuncSetAttribute(k_gemm_tc_h, cudaFuncAttributeMaxDynamicSharedMemorySize, GEMM_SMEM);

  const int gblocks = (NN + 127) / 128;       // 782
  const int eblocks1 = (NE + 511) / 512;      // 3125
  const int eblocks4 = (NE / 4 + 511) / 512;  // 782

  // ---- fork: CSR build (+W2 convert) on side stream, GEMM1 on main ----
  cudaEventRecord(g_ev_fork, 0);
  cudaStreamWaitEvent(g_side, g_ev_fork, 0);

  k_hist<<<eblocks4, 512, 0, g_side>>>(row, W2, w2h);
  k_scanA<<<NBLK, SCAN_B, 0, g_side>>>();
  k_scanBC<<<NBLK, SCAN_B, 0, g_side>>>();
  k_place<<<eblocks1, 512, 0, g_side>>>(row, col);
  cudaEventRecord(g_ev_csr, g_side);

  k_gemm_tc<<<gblocks, 256, GEMM_SMEM>>>(x, W1, b1, h, NN);      // h = x W1^T + b1

  // ---- join, then the dependent chain ----
  cudaStreamWaitEvent(0, g_ev_csr, 0);
  k_gather<0><<<(NN + 7) / 8, 256>>>(h, agg);                    // agg = elu(mean(h)) [fp16]
  k_gemm_tc_h<<<gblocks, 256, GEMM_SMEM>>>(agg, w2h, b2, h, NN); // h = agg W2h^T + b2
  k_gather<1><<<(NN + 7) / 8, 256>>>(h, out);                    // out = mean(h) [fp32]
}